// round 1
// baseline (speedup 1.0000x reference)
#include <cuda_runtime.h>

#define T_STEPS 256
#define B_SZ    128
#define H_SZ    1024
#define D_SZ    1024
#define TB      (T_STEPS * B_SZ)   // 32768 rows

// ---------------- scratch (static device globals; no allocs) ----------------
__device__ __align__(16) float g_Wqi[4 * D_SZ];   // (Wq @ Wi)[k, d]
__device__ float g_rowsumWh[H_SZ];                // sum_h Wh[j, h]
__device__ float g_bsum[H_SZ];                    // bi + bh
__device__ float g_coef[8];                       // [0..3]=wsum_k, [4..7]=cbias_k (+bq+theta)
__device__ __align__(16) float g_xq[TB * 4];      // per-(t,b) 4 pre-activations (incl. bias+theta)
__device__ float g_Hs[TB];                        // Hs[t*B+b] = hx scalar
__device__ float g_fin[2 * B_SZ];                 // [0..127]=Hs final, [128..255]=C final

__device__ __forceinline__ float warp_sum(float v) {
    v += __shfl_down_sync(0xffffffffu, v, 16);
    v += __shfl_down_sync(0xffffffffu, v, 8);
    v += __shfl_down_sync(0xffffffffu, v, 4);
    v += __shfl_down_sync(0xffffffffu, v, 2);
    v += __shfl_down_sync(0xffffffffu, v, 1);
    return v;
}

// tanh via exp2-based __expf: |err| ~1e-7, far below tolerance
__device__ __forceinline__ float tanh_fast(float x) {
    float e = __expf(2.0f * x);
    return 1.0f - __fdividef(2.0f, e + 1.0f);
}

// ---------------- K1: row sums of Wh, bias sum ----------------
__global__ void k_rowsum(const float* __restrict__ Wh,
                         const float* __restrict__ bi,
                         const float* __restrict__ bh) {
    int j = blockIdx.x;                       // 1024 blocks, 256 threads
    const float4* w4 = (const float4*)(Wh + (size_t)j * H_SZ);
    float4 v = w4[threadIdx.x];
    float s = (v.x + v.y) + (v.z + v.w);
    s = warp_sum(s);
    __shared__ float sh[8];
    if ((threadIdx.x & 31) == 0) sh[threadIdx.x >> 5] = s;
    __syncthreads();
    if (threadIdx.x == 0) {
        float t = 0.f;
#pragma unroll
        for (int w = 0; w < 8; w++) t += sh[w];
        g_rowsumWh[j] = t;
        g_bsum[j] = bi[j] + bh[j];
    }
}

// ---------------- K2: Wqi = Wq @ Wi  (4 x 1024) ----------------
__global__ void __launch_bounds__(256) k_wqi(const float* __restrict__ Wi,
                                             const float* __restrict__ Wq) {
    __shared__ float sWq[H_SZ];
    int k = blockIdx.x >> 2;                          // 16 blocks: 4 per k
    int d = ((blockIdx.x & 3) << 8) | threadIdx.x;    // 256 d per block
    for (int i = threadIdx.x; i < H_SZ; i += 256) sWq[i] = Wq[k * H_SZ + i];
    __syncthreads();
    float acc = 0.f;
#pragma unroll 8
    for (int j = 0; j < H_SZ; j++)
        acc = fmaf(sWq[j], __ldg(Wi + (size_t)j * D_SZ + d), acc);
    g_Wqi[k * D_SZ + d] = acc;
}

// ---------------- K3: wsum, cbias (folds bq and theta) ----------------
__global__ void k_coef(const float* __restrict__ Wq,
                       const float* __restrict__ bq,
                       const float* __restrict__ theta) {
    int k = threadIdx.x >> 5, lane = threadIdx.x & 31;   // 128 threads = 4 warps
    float a1 = 0.f, a2 = 0.f;
    for (int j = lane; j < H_SZ; j += 32) {
        float q = Wq[k * H_SZ + j];
        a1 = fmaf(q, g_rowsumWh[j], a1);
        a2 = fmaf(q, g_bsum[j], a2);
    }
    a1 = warp_sum(a1);
    a2 = warp_sum(a2);
    if (lane == 0) {
        g_coef[k] = a1;                          // wsum_k
        g_coef[4 + k] = a2 + bq[k] + theta[k];   // cbias_k (+theta folded into angle)
    }
}

// ---------------- K4: xq[t,b,k] = inputs row · Wqi[k] + cbias[k] ----------------
// Skinny GEMM [32768,1024] @ [1024,4]; weights in registers, DRAM-bound.
__global__ void __launch_bounds__(256) k_xq(const float* __restrict__ inp) {
    const int tid = threadIdx.x, wid = tid >> 5, lane = tid & 31;
    float4 w0 = *(const float4*)&g_Wqi[0 * D_SZ + tid * 4];
    float4 w1 = *(const float4*)&g_Wqi[1 * D_SZ + tid * 4];
    float4 w2 = *(const float4*)&g_Wqi[2 * D_SZ + tid * 4];
    float4 w3 = *(const float4*)&g_Wqi[3 * D_SZ + tid * 4];
    __shared__ float red[16][9];
    const float4* in4 = (const float4*)inp;
    int rowBase = blockIdx.x * 64;                // 512 blocks * 64 rows

    for (int rb = 0; rb < 16; rb++) {
        int r0 = rowBase + rb * 4;
        float a[4][4];
#pragma unroll
        for (int r = 0; r < 4; r++) {
            float4 x = __ldcs(&in4[(size_t)(r0 + r) * 256 + tid]);
            a[r][0] = fmaf(x.x, w0.x, fmaf(x.y, w0.y, fmaf(x.z, w0.z, x.w * w0.w)));
            a[r][1] = fmaf(x.x, w1.x, fmaf(x.y, w1.y, fmaf(x.z, w1.z, x.w * w1.w)));
            a[r][2] = fmaf(x.x, w2.x, fmaf(x.y, w2.y, fmaf(x.z, w2.z, x.w * w2.w)));
            a[r][3] = fmaf(x.x, w3.x, fmaf(x.y, w3.y, fmaf(x.z, w3.z, x.w * w3.w)));
        }
#pragma unroll
        for (int r = 0; r < 4; r++)
#pragma unroll
            for (int k = 0; k < 4; k++) {
                float v = warp_sum(a[r][k]);
                if (lane == 0) red[r * 4 + k][wid] = v;
            }
        __syncthreads();
        if (tid < 16) {
            float v = 0.f;
#pragma unroll
            for (int w = 0; w < 8; w++) v += red[tid][w];
            int r = tid >> 2, k = tid & 3;
            g_xq[(size_t)(r0 + r) * 4 + k] = v + g_coef[4 + k];
        }
        __syncthreads();
    }
}

// ---------------- K5: the whole recurrence, scalar per batch row ----------------
// Quantum circuit closed form: z_k = cos(angle_k);
// exps = [z1*z2*z3, z0*z1, z0*z1*z2, z0*z1*z2*z3]; softmax -> (f,i,g,o)
__global__ void k_rec() {
    int b = blockIdx.x * 32 + threadIdx.x;        // 4 blocks x 32 threads = 128 rows
    float ws0 = g_coef[0], ws1 = g_coef[1], ws2 = g_coef[2], ws3 = g_coef[3];
    float C = 0.f, Hs = 0.f;
    const float4* xq4 = (const float4*)g_xq;
    for (int t = 0; t < T_STEPS; t++) {
        float4 x = xq4[t * B_SZ + b];
        float a0 = fmaf(Hs, ws0, x.x);
        float a1 = fmaf(Hs, ws1, x.y);
        float a2 = fmaf(Hs, ws2, x.z);
        float a3 = fmaf(Hs, ws3, x.w);
        float z0 = __cosf(a0), z1 = __cosf(a1), z2 = __cosf(a2), z3 = __cosf(a3);
        float t12 = z1 * z2;
        float e1 = z0 * z1;
        float e0 = t12 * z3;
        float e2 = z0 * t12;
        float e3 = e2 * z3;
        // |e| <= 1, so softmax without max-subtraction is safe
        float p0 = __expf(e0), p1 = __expf(e1), p2 = __expf(e2), p3 = __expf(e3);
        float s = (p0 + p1) + (p2 + p3);
        float inv = __fdividef(1.0f, s);
        float f  = p0 * inv;
        float i_ = p1 * inv;
        float g  = p2 * inv;
        float o  = p3 * inv;
        C = fmaf(f, C, i_ * tanh_fast(g));
        Hs = o * tanh_fast(C);
        g_Hs[t * B_SZ + b] = Hs;
    }
    g_fin[b] = Hs;
    g_fin[B_SZ + b] = C;
}

// ---------------- K6: broadcast writes: ys, hx, cx ----------------
__global__ void __launch_bounds__(256) k_out(float* __restrict__ out) {
    int row = blockIdx.x;                          // TB + 256 blocks
    float v = (row < TB) ? g_Hs[row] : g_fin[row - TB];
    float4 vv = make_float4(v, v, v, v);
    float4* o4 = (float4*)out;
    __stcs(&o4[(size_t)row * 256 + threadIdx.x], vv);
}

// ---------------- launch ----------------
extern "C" void kernel_launch(void* const* d_in, const int* in_sizes, int n_in,
                              void* d_out, int out_size) {
    const float* inputs = (const float*)d_in[0];
    const float* Wi     = (const float*)d_in[1];
    const float* bi     = (const float*)d_in[2];
    const float* Wh     = (const float*)d_in[3];
    const float* bh     = (const float*)d_in[4];
    const float* Wq     = (const float*)d_in[5];
    const float* bq     = (const float*)d_in[6];
    const float* theta  = (const float*)d_in[7];
    float* out = (float*)d_out;

    k_rowsum<<<H_SZ, 256>>>(Wh, bi, bh);
    k_wqi<<<16, 256>>>(Wi, Wq);
    k_coef<<<1, 128>>>(Wq, bq, theta);
    k_xq<<<512, 256>>>(inputs);
    k_rec<<<4, 32>>>();
    k_out<<<TB + 2 * B_SZ, 256>>>(out);
}

// round 2
// speedup vs baseline: 2.2255x; 2.2255x over previous
#include <cuda_runtime.h>

#define T_STEPS 256
#define B_SZ    128
#define TB      (T_STEPS * B_SZ)     // 32768 rows
#define H_SZ    1024
#define D_SZ    1024
#define N_CHUNK 1024                 // 32 rows per chunk
#define ROWS_PER_CHUNK 32
#define CHUNKS_PER_T 4
#define N_WORK  296                  // xq worker blocks (2/SM)

// ---------------- static device scratch ----------------
__device__ __align__(16) float g_Wqi[4 * D_SZ];
__device__ __align__(16) float g_part[32 * 4 * D_SZ];   // [jc][k][d]
__device__ float g_rowsumWh[H_SZ];
__device__ float g_bsum[H_SZ];
__device__ float g_coef[8];                 // [0..3]=wsum_k, [4..7]=cbias_k
__device__ __align__(16) float g_xq[TB * 4];
__device__ float g_Hs[TB];
__device__ float g_fin[2 * B_SZ];
__device__ int   g_ready[T_STEPS];          // per-t completion counters
__device__ int   g_work;                    // chunk work queue

// ---------------- helpers ----------------
__device__ __forceinline__ float warp_sum(float v) {
    v += __shfl_down_sync(0xffffffffu, v, 16);
    v += __shfl_down_sync(0xffffffffu, v, 8);
    v += __shfl_down_sync(0xffffffffu, v, 4);
    v += __shfl_down_sync(0xffffffffu, v, 2);
    v += __shfl_down_sync(0xffffffffu, v, 1);
    return v;
}
__device__ __forceinline__ float tanh_fast(float x) {
    float e = __expf(2.0f * x);
    return 1.0f - __fdividef(2.0f, e + 1.0f);
}
__device__ __forceinline__ int ld_acquire_gpu(const int* p) {
    int v;
    asm volatile("ld.acquire.gpu.global.b32 %0, [%1];" : "=r"(v) : "l"(p) : "memory");
    return v;
}
__device__ __forceinline__ int ld_acquire_cta_shared(unsigned fa) {
    int v;
    asm volatile("ld.acquire.cta.shared.b32 %0, [%1];" : "=r"(v) : "r"(fa) : "memory");
    return v;
}
__device__ __forceinline__ void st_release_cta_shared(unsigned fa, int v) {
    asm volatile("st.release.cta.shared.b32 [%0], %1;" :: "r"(fa), "r"(v) : "memory");
}
__device__ __forceinline__ void wait_front(unsigned fa, int need) {
    if (ld_acquire_cta_shared(fa) >= need) return;
    while (ld_acquire_cta_shared(fa) < need) __nanosleep(32);
}

// ---------------- K1: row sums of Wh, bias sum, flag/queue reset ----------------
__global__ void k_rowsum(const float* __restrict__ Wh,
                         const float* __restrict__ bi,
                         const float* __restrict__ bh) {
    int j = blockIdx.x;                       // 1024 blocks, 256 threads
    if (j == 0) g_ready[threadIdx.x] = 0;     // reset pipeline flags each launch
    if (j == 1 && threadIdx.x == 0) g_work = 0;
    const float4* w4 = (const float4*)(Wh + (size_t)j * H_SZ);
    float4 v = w4[threadIdx.x];
    float s = (v.x + v.y) + (v.z + v.w);
    s = warp_sum(s);
    __shared__ float sh[8];
    if ((threadIdx.x & 31) == 0) sh[threadIdx.x >> 5] = s;
    __syncthreads();
    if (threadIdx.x == 0) {
        float t = 0.f;
#pragma unroll
        for (int w = 0; w < 8; w++) t += sh[w];
        g_rowsumWh[j] = t;
        g_bsum[j] = bi[j] + bh[j];
    }
}

// ---------------- K2a: partials of Wqi = Wq @ Wi ----------------
__global__ void __launch_bounds__(256) k_wqiA(const float* __restrict__ Wi,
                                              const float* __restrict__ Wq) {
    __shared__ float sq[4][32];
    int jc = blockIdx.x >> 2, dc = blockIdx.x & 3;    // 128 blocks
    int d = dc * 256 + threadIdx.x;
    if (threadIdx.x < 128)
        sq[threadIdx.x >> 5][threadIdx.x & 31] = Wq[(threadIdx.x >> 5) * H_SZ + jc * 32 + (threadIdx.x & 31)];
    __syncthreads();
    float a0 = 0.f, a1 = 0.f, a2 = 0.f, a3 = 0.f;
#pragma unroll
    for (int jj = 0; jj < 32; jj++) {
        float wv = __ldg(Wi + (size_t)(jc * 32 + jj) * D_SZ + d);
        a0 = fmaf(sq[0][jj], wv, a0);
        a1 = fmaf(sq[1][jj], wv, a1);
        a2 = fmaf(sq[2][jj], wv, a2);
        a3 = fmaf(sq[3][jj], wv, a3);
    }
    g_part[(jc * 4 + 0) * D_SZ + d] = a0;
    g_part[(jc * 4 + 1) * D_SZ + d] = a1;
    g_part[(jc * 4 + 2) * D_SZ + d] = a2;
    g_part[(jc * 4 + 3) * D_SZ + d] = a3;
}

// ---------------- K2b: combine partials ----------------
__global__ void __launch_bounds__(256) k_wqiB() {
    int k = blockIdx.x >> 2, dc = blockIdx.x & 3;     // 16 blocks
    int d = dc * 256 + threadIdx.x;
    float v = 0.f;
#pragma unroll
    for (int jc = 0; jc < 32; jc++) v += g_part[(jc * 4 + k) * D_SZ + d];
    g_Wqi[k * D_SZ + d] = v;
}

// ---------------- K3: wsum, cbias ----------------
__global__ void k_coef(const float* __restrict__ Wq,
                       const float* __restrict__ bq,
                       const float* __restrict__ theta) {
    int k = threadIdx.x >> 5, lane = threadIdx.x & 31;   // 128 threads
    float a1 = 0.f, a2 = 0.f;
    for (int j = lane; j < H_SZ; j += 32) {
        float q = Wq[k * H_SZ + j];
        a1 = fmaf(q, g_rowsumWh[j], a1);
        a2 = fmaf(q, g_bsum[j], a2);
    }
    a1 = warp_sum(a1);
    a2 = warp_sum(a2);
    if (lane == 0) {
        g_coef[k] = a1;
        g_coef[4 + k] = a2 + bq[k] + theta[k];
    }
}

// ---------------- rec step (closed-form circuit + LSTM update) ----------------
__device__ __forceinline__ void rec_step(float4 x, float ws0, float ws1, float ws2, float ws3,
                                         float& C, float& Hs) {
    float a0 = fmaf(Hs, ws0, x.x);
    float a1 = fmaf(Hs, ws1, x.y);
    float a2 = fmaf(Hs, ws2, x.z);
    float a3 = fmaf(Hs, ws3, x.w);
    float z0 = __cosf(a0), z1 = __cosf(a1), z2 = __cosf(a2), z3 = __cosf(a3);
    float t12 = z1 * z2;
    float e1 = z0 * z1;
    float e0 = t12 * z3;
    float e2 = z0 * t12;
    float e3 = e2 * z3;
    float p0 = __expf(e0), p1 = __expf(e1), p2 = __expf(e2), p3 = __expf(e3);
    float s = (p0 + p1) + (p2 + p3);
    float inv = __fdividef(1.0f, s);
    float f = p0 * inv, i_ = p1 * inv, g = p2 * inv, o = p3 * inv;
    C = fmaf(f, C, i_ * tanh_fast(g));
    Hs = o * tanh_fast(C);
}

// ---------------- K4: fused xq GEMV + pipelined recurrence ----------------
__global__ void __launch_bounds__(256) k_main(const float* __restrict__ inp) {
    __shared__ float red[8][4][8];
    __shared__ int s_chunk;
    __shared__ int s_front;
    const int tid = threadIdx.x, lane = tid & 31, wid = tid >> 5;

    if (blockIdx.x == 0) {
        // ---------- recurrence block ----------
        if (tid == 0) s_front = 0;
        __syncthreads();
        unsigned fa = (unsigned)__cvta_generic_to_shared(&s_front);

        if (tid >= 128 && tid < 160) {
            // publisher warp: flags -> monotone frontier
            int pl = tid - 128;
            int base = 0;
            while (base < T_STEPS) {
                int t = base + pl;
                int v = (t < T_STEPS) ? ld_acquire_gpu(&g_ready[t]) : CHUNKS_PER_T;
                unsigned m = __ballot_sync(0xffffffffu, v >= CHUNKS_PER_T);
                int n;
                if (~m == 0u) n = 32;
                else n = __ffs(~m) - 1;
                if (n > 0) {
                    if (pl == 0) st_release_cta_shared(fa, base + n);
                    base += n;
                } else {
                    __nanosleep(64);
                }
            }
            return;
        }
        if (tid >= 128) return;

        // consumer: 128 threads = 128 batch rows
        const int b = tid;
        const float ws0 = g_coef[0], ws1 = g_coef[1], ws2 = g_coef[2], ws3 = g_coef[3];
        const float4* xq4 = (const float4*)g_xq;
        float C = 0.f, Hs = 0.f;
        float4 bufa[4], bufb[4];
        wait_front(fa, 8);
#pragma unroll
        for (int j = 0; j < 4; j++) {
            bufa[j] = __ldcg(&xq4[j * B_SZ + b]);
            bufb[j] = __ldcg(&xq4[(4 + j) * B_SZ + b]);
        }
        for (int u2 = 0; u2 < 32; u2++) {
            int tb = u2 * 8;
            // --- steps tb..tb+3 from bufa ---
            {
                int need = tb + 12; if (need > T_STEPS) need = T_STEPS;
                if (tb + 8 < T_STEPS) wait_front(fa, need);
#pragma unroll
                for (int j = 0; j < 4; j++) {
                    float4 x = bufa[j];
                    int tn = tb + 8 + j;
                    if (tn < T_STEPS) bufa[j] = __ldcg(&xq4[tn * B_SZ + b]);
                    rec_step(x, ws0, ws1, ws2, ws3, C, Hs);
                    g_Hs[(tb + j) * B_SZ + b] = Hs;
                }
            }
            // --- steps tb+4..tb+7 from bufb ---
            {
                int tb2 = tb + 4;
                int need = tb2 + 12; if (need > T_STEPS) need = T_STEPS;
                if (tb2 + 8 < T_STEPS) wait_front(fa, need);
#pragma unroll
                for (int j = 0; j < 4; j++) {
                    float4 x = bufb[j];
                    int tn = tb2 + 8 + j;
                    if (tn < T_STEPS) bufb[j] = __ldcg(&xq4[tn * B_SZ + b]);
                    rec_step(x, ws0, ws1, ws2, ws3, C, Hs);
                    g_Hs[(tb2 + j) * B_SZ + b] = Hs;
                }
            }
        }
        g_fin[b] = Hs;
        g_fin[B_SZ + b] = C;
        return;
    }

    // ---------- xq worker blocks ----------
    const float4* wq4 = (const float4*)g_Wqi;
    float4 w0 = wq4[0 * 256 + tid];
    float4 w1 = wq4[1 * 256 + tid];
    float4 w2 = wq4[2 * 256 + tid];
    float4 w3 = wq4[3 * 256 + tid];
    const float4* in4 = (const float4*)inp;

    while (true) {
        if (tid == 0) s_chunk = atomicAdd(&g_work, 1);
        __syncthreads();
        int c = s_chunk;
        if (c >= N_CHUNK) break;
        int rowBase = c * ROWS_PER_CHUNK;

        for (int bt = 0; bt < 4; bt++) {
            int r0 = rowBase + bt * 8;
            float4 xr[8];
#pragma unroll
            for (int r = 0; r < 8; r++)
                xr[r] = __ldcs(&in4[(size_t)(r0 + r) * 256 + tid]);
#pragma unroll
            for (int r = 0; r < 8; r++) {
                float4 x = xr[r];
                float a0 = fmaf(x.x, w0.x, fmaf(x.y, w0.y, fmaf(x.z, w0.z, x.w * w0.w)));
                float a1 = fmaf(x.x, w1.x, fmaf(x.y, w1.y, fmaf(x.z, w1.z, x.w * w1.w)));
                float a2 = fmaf(x.x, w2.x, fmaf(x.y, w2.y, fmaf(x.z, w2.z, x.w * w2.w)));
                float a3 = fmaf(x.x, w3.x, fmaf(x.y, w3.y, fmaf(x.z, w3.z, x.w * w3.w)));
                // packed tree: demultiplex k during reduction (21 ops vs 40)
                float o0 = __shfl_xor_sync(0xffffffffu, a0, 16);
                float o1 = __shfl_xor_sync(0xffffffffu, a1, 16);
                float o2 = __shfl_xor_sync(0xffffffffu, a2, 16);
                float o3 = __shfl_xor_sync(0xffffffffu, a3, 16);
                bool hi = lane >= 16;
                float b0 = hi ? (a2 + o2) : (a0 + o0);
                float b1 = hi ? (a3 + o3) : (a1 + o1);
                float q0 = __shfl_xor_sync(0xffffffffu, b0, 8);
                float q1 = __shfl_xor_sync(0xffffffffu, b1, 8);
                float cc = (lane & 8) ? (b1 + q1) : (b0 + q0);
                cc += __shfl_xor_sync(0xffffffffu, cc, 4);
                cc += __shfl_xor_sync(0xffffffffu, cc, 2);
                cc += __shfl_xor_sync(0xffffffffu, cc, 1);
                if ((lane & 7) == 0) red[r][lane >> 3][wid] = cc;
            }
            __syncthreads();
            if (tid < 32) {
                int r = tid >> 2, k = tid & 3;
                float v = 0.f;
#pragma unroll
                for (int w = 0; w < 8; w++) v += red[r][k][w];
                g_xq[(size_t)(r0 + r) * 4 + k] = v + g_coef[4 + k];
            }
            __syncthreads();
        }
        if (tid == 0) {
            __threadfence();
            atomicAdd(&g_ready[c >> 2], 1);   // t = chunk/4
        }
    }
}

// ---------------- K5: broadcast writes: ys, hx, cx ----------------
__global__ void __launch_bounds__(256) k_out(float* __restrict__ out) {
    int row = blockIdx.x;                          // TB + 256 blocks
    float v = (row < TB) ? g_Hs[row] : g_fin[row - TB];
    float4 vv = make_float4(v, v, v, v);
    float4* o4 = (float4*)out;
    __stcs(&o4[(size_t)row * 256 + threadIdx.x], vv);
}

// ---------------- launch ----------------
extern "C" void kernel_launch(void* const* d_in, const int* in_sizes, int n_in,
                              void* d_out, int out_size) {
    const float* inputs = (const float*)d_in[0];
    const float* Wi     = (const float*)d_in[1];
    const float* bi     = (const float*)d_in[2];
    const float* Wh     = (const float*)d_in[3];
    const float* bh     = (const float*)d_in[4];
    const float* Wq     = (const float*)d_in[5];
    const float* bq     = (const float*)d_in[6];
    const float* theta  = (const float*)d_in[7];
    float* out = (float*)d_out;

    k_rowsum<<<H_SZ, 256>>>(Wh, bi, bh);
    k_wqiA<<<128, 256>>>(Wi, Wq);
    k_wqiB<<<16, 256>>>();
    k_coef<<<1, 128>>>(Wq, bq, theta);
    k_main<<<N_WORK + 1, 256>>>(inputs);
    k_out<<<TB + 2 * B_SZ, 256>>>(out);
}

// round 4
// speedup vs baseline: 2.2663x; 1.0184x over previous
#include <cuda_runtime.h>

#define T_STEPS 256
#define B_SZ    128
#define TB      (T_STEPS * B_SZ)     // 32768 rows
#define H_SZ    1024
#define D_SZ    1024
#define N_CHUNK 1024                 // GEMV: 32 rows per chunk
#define ROWS_PER_CHUNK 32
#define CHUNKS_PER_T 4
#define N_WORK  295                  // worker blocks; +1 rec block = 296 = wave-1
#define N_OCHUNK ((TB + 2 * B_SZ) / 32)   // 1032 output chunks of 32 rows

// ---------------- static device scratch ----------------
__device__ __align__(16) float g_Wqi[4 * D_SZ];
__device__ __align__(16) float g_part[32 * 4 * D_SZ];   // [jc][k][d]
__device__ float g_rowsumWh[H_SZ];
__device__ float g_bsum[H_SZ];
__device__ float g_coef[8];                 // [0..3]=wsum_k, [4..7]=cbias_k
__device__ __align__(16) float g_xq[TB * 4];
__device__ float g_Hs[TB];
__device__ float g_fin[2 * B_SZ];
__device__ int   g_ready[T_STEPS];          // per-t GEMV completion counters
__device__ int   g_work;                    // GEMV chunk queue
__device__ int   g_owork;                   // output chunk queue
__device__ int   g_outfront;                // rec progress (t's fully published)

// ---------------- helpers ----------------
__device__ __forceinline__ float warp_sum(float v) {
    v += __shfl_down_sync(0xffffffffu, v, 16);
    v += __shfl_down_sync(0xffffffffu, v, 8);
    v += __shfl_down_sync(0xffffffffu, v, 4);
    v += __shfl_down_sync(0xffffffffu, v, 2);
    v += __shfl_down_sync(0xffffffffu, v, 1);
    return v;
}
__device__ __forceinline__ float tanh_fast(float x) {
    float e = __expf(2.0f * x);
    return 1.0f - __fdividef(2.0f, e + 1.0f);
}
__device__ __forceinline__ int ld_acquire_gpu(const int* p) {
    int v;
    asm volatile("ld.acquire.gpu.global.b32 %0, [%1];" : "=r"(v) : "l"(p) : "memory");
    return v;
}
__device__ __forceinline__ void st_release_gpu(int* p, int v) {
    asm volatile("st.release.gpu.global.b32 [%0], %1;" :: "l"(p), "r"(v) : "memory");
}
__device__ __forceinline__ int ld_acquire_cta_shared(unsigned fa) {
    int v;
    asm volatile("ld.acquire.cta.shared.b32 %0, [%1];" : "=r"(v) : "r"(fa) : "memory");
    return v;
}
__device__ __forceinline__ void st_release_cta_shared(unsigned fa, int v) {
    asm volatile("st.release.cta.shared.b32 [%0], %1;" :: "r"(fa), "r"(v) : "memory");
}
__device__ __forceinline__ void wait_front(unsigned fa, int need) {
    if (ld_acquire_cta_shared(fa) >= need) return;
    while (ld_acquire_cta_shared(fa) < need) __nanosleep(32);
}
__device__ __forceinline__ void wait_gfront(const int* p, int need) {
    if (ld_acquire_gpu(p) >= need) return;
    while (ld_acquire_gpu(p) < need) __nanosleep(64);
}

// ---------------- K1: rowsum(Wh)+bsum  ||  Wqi partials  ||  flag reset ------
__global__ void __launch_bounds__(256) k_pre1(const float* __restrict__ Wh,
                                              const float* __restrict__ bi,
                                              const float* __restrict__ bh,
                                              const float* __restrict__ Wi,
                                              const float* __restrict__ Wq) {
    __shared__ float sh[8];
    __shared__ float sq[4][32];
    int bid = blockIdx.x;
    if (bid < H_SZ) {
        // ---- row sums of Wh ----
        int j = bid;
        if (j == 0) g_ready[threadIdx.x] = 0;
        if (j == 1 && threadIdx.x == 0) { g_work = 0; g_owork = 0; g_outfront = 0; }
        const float4* w4 = (const float4*)(Wh + (size_t)j * H_SZ);
        float4 v = w4[threadIdx.x];
        float s = (v.x + v.y) + (v.z + v.w);
        s = warp_sum(s);
        if ((threadIdx.x & 31) == 0) sh[threadIdx.x >> 5] = s;
        __syncthreads();
        if (threadIdx.x == 0) {
            float t = 0.f;
#pragma unroll
            for (int w = 0; w < 8; w++) t += sh[w];
            g_rowsumWh[j] = t;
            g_bsum[j] = bi[j] + bh[j];
        }
    } else {
        // ---- partials of Wqi = Wq @ Wi ----
        int p = bid - H_SZ;                       // 128 blocks
        int jc = p >> 2, dc = p & 3;
        int d = dc * 256 + threadIdx.x;
        if (threadIdx.x < 128)
            sq[threadIdx.x >> 5][threadIdx.x & 31] =
                Wq[(threadIdx.x >> 5) * H_SZ + jc * 32 + (threadIdx.x & 31)];
        __syncthreads();
        float a0 = 0.f, a1 = 0.f, a2 = 0.f, a3 = 0.f;
#pragma unroll
        for (int jj = 0; jj < 32; jj++) {
            float wv = __ldg(Wi + (size_t)(jc * 32 + jj) * D_SZ + d);
            a0 = fmaf(sq[0][jj], wv, a0);
            a1 = fmaf(sq[1][jj], wv, a1);
            a2 = fmaf(sq[2][jj], wv, a2);
            a3 = fmaf(sq[3][jj], wv, a3);
        }
        g_part[(jc * 4 + 0) * D_SZ + d] = a0;
        g_part[(jc * 4 + 1) * D_SZ + d] = a1;
        g_part[(jc * 4 + 2) * D_SZ + d] = a2;
        g_part[(jc * 4 + 3) * D_SZ + d] = a3;
    }
}

// ---------------- K2: combine Wqi partials || coef --------------------------
__global__ void __launch_bounds__(256) k_pre2(const float* __restrict__ Wq,
                                              const float* __restrict__ bq,
                                              const float* __restrict__ theta) {
    __shared__ float s1[8], s2[8];
    int bid = blockIdx.x;
    if (bid < 16) {
        int k = bid >> 2, dc = bid & 3;
        int d = dc * 256 + threadIdx.x;
        float v = 0.f;
#pragma unroll
        for (int jc = 0; jc < 32; jc++) v += g_part[(jc * 4 + k) * D_SZ + d];
        g_Wqi[k * D_SZ + d] = v;
    } else {
        // coef: block per k, 256 threads, 4 elems each
        int k = bid - 16;
        int lane = threadIdx.x & 31, wid = threadIdx.x >> 5;
        float a1 = 0.f, a2 = 0.f;
#pragma unroll
        for (int it = 0; it < 4; it++) {
            int j = it * 256 + threadIdx.x;
            float q = __ldg(Wq + k * H_SZ + j);
            a1 = fmaf(q, g_rowsumWh[j], a1);
            a2 = fmaf(q, g_bsum[j], a2);
        }
        a1 = warp_sum(a1);
        a2 = warp_sum(a2);
        if (lane == 0) { s1[wid] = a1; s2[wid] = a2; }
        __syncthreads();
        if (threadIdx.x == 0) {
            float t1 = 0.f, t2 = 0.f;
#pragma unroll
            for (int w = 0; w < 8; w++) { t1 += s1[w]; t2 += s2[w]; }
            g_coef[k] = t1;
            g_coef[4 + k] = t2 + bq[k] + theta[k];
        }
    }
}

// ---------------- rec step (closed-form circuit + LSTM update) ---------------
__device__ __forceinline__ void rec_step(float4 x, float ws0, float ws1, float ws2, float ws3,
                                         float& C, float& Hs) {
    float a0 = fmaf(Hs, ws0, x.x);
    float a1 = fmaf(Hs, ws1, x.y);
    float a2 = fmaf(Hs, ws2, x.z);
    float a3 = fmaf(Hs, ws3, x.w);
    float z0 = __cosf(a0), z1 = __cosf(a1), z2 = __cosf(a2), z3 = __cosf(a3);
    float t12 = z1 * z2;
    float e1 = z0 * z1;
    float e0 = t12 * z3;
    float e2 = z0 * t12;
    float e3 = e2 * z3;
    float p0 = __expf(e0), p1 = __expf(e1), p2 = __expf(e2), p3 = __expf(e3);
    float s = (p0 + p1) + (p2 + p3);
    float inv = __fdividef(1.0f, s);
    float f = p0 * inv, i_ = p1 * inv, g = p2 * inv, o = p3 * inv;
    C = fmaf(f, C, i_ * tanh_fast(g));
    Hs = o * tanh_fast(C);
}

// ---------------- K3: fused GEMV + recurrence + output broadcast -------------
__global__ void __launch_bounds__(256) k_main(const float* __restrict__ inp,
                                              float* __restrict__ out) {
    __shared__ float red[8][4][8];
    __shared__ int s_chunk;
    __shared__ int s_front;
    const int tid = threadIdx.x, lane = tid & 31, wid = tid >> 5;

    if (blockIdx.x == 0) {
        // ================= recurrence block =================
        if (tid == 0) s_front = 0;
        __syncthreads();
        unsigned fa = (unsigned)__cvta_generic_to_shared(&s_front);

        if (tid >= 128 && tid < 160) {
            // publisher warp: g_ready flags -> monotone smem frontier
            int pl = tid - 128;
            int base = 0;
            while (base < T_STEPS) {
                int t = base + pl;
                int v = (t < T_STEPS) ? ld_acquire_gpu(&g_ready[t]) : CHUNKS_PER_T;
                unsigned m = __ballot_sync(0xffffffffu, v >= CHUNKS_PER_T);
                int n = (~m == 0u) ? 32 : (__ffs(~m) - 1);
                if (n > 0) {
                    if (pl == 0) st_release_cta_shared(fa, base + n);
                    base += n;
                } else {
                    __nanosleep(64);
                }
            }
            return;
        }
        if (tid >= 128) return;

        // consumer warps: 128 threads = 128 batch rows
        const int b = tid;
        const float ws0 = g_coef[0], ws1 = g_coef[1], ws2 = g_coef[2], ws3 = g_coef[3];
        const float4* xq4 = (const float4*)g_xq;
        float C = 0.f, Hs = 0.f;
        float4 bufa[4], bufb[4];
        wait_front(fa, 8);
#pragma unroll
        for (int j = 0; j < 4; j++) {
            bufa[j] = __ldcg(&xq4[j * B_SZ + b]);
            bufb[j] = __ldcg(&xq4[(4 + j) * B_SZ + b]);
        }
        for (int u2 = 0; u2 < 32; u2++) {
            int tb = u2 * 8;
            {
                int need = tb + 12; if (need > T_STEPS) need = T_STEPS;
                if (tb + 8 < T_STEPS) wait_front(fa, need);
#pragma unroll
                for (int j = 0; j < 4; j++) {
                    float4 x = bufa[j];
                    int tn = tb + 8 + j;
                    if (tn < T_STEPS) bufa[j] = __ldcg(&xq4[tn * B_SZ + b]);
                    rec_step(x, ws0, ws1, ws2, ws3, C, Hs);
                    __stcg(&g_Hs[(tb + j) * B_SZ + b], Hs);   // L2-visible for consumers
                }
            }
            {
                int tb2 = tb + 4;
                int need = tb2 + 12; if (need > T_STEPS) need = T_STEPS;
                if (tb2 + 8 < T_STEPS) wait_front(fa, need);
#pragma unroll
                for (int j = 0; j < 4; j++) {
                    float4 x = bufb[j];
                    int tn = tb2 + 8 + j;
                    if (tn < T_STEPS) bufb[j] = __ldcg(&xq4[tn * B_SZ + b]);
                    rec_step(x, ws0, ws1, ws2, ws3, C, Hs);
                    __stcg(&g_Hs[(tb2 + j) * B_SZ + b], Hs);
                }
            }
            // publish completed t's (GPU scope) every 8 steps
            asm volatile("bar.sync 1, 128;" ::: "memory");
            if (tid == 0) st_release_gpu(&g_outfront, tb + 8);
        }
        __stcg(&g_fin[b], Hs);
        __stcg(&g_fin[B_SZ + b], C);
        asm volatile("bar.sync 1, 128;" ::: "memory");
        if (tid == 0) st_release_gpu(&g_outfront, T_STEPS + 1);   // tail sentinel
        return;
    }

    // ================= worker blocks =================
    const float4* wq4 = (const float4*)g_Wqi;
    float4 w0 = wq4[0 * 256 + tid];
    float4 w1 = wq4[1 * 256 + tid];
    float4 w2 = wq4[2 * 256 + tid];
    float4 w3 = wq4[3 * 256 + tid];
    const float4* in4 = (const float4*)inp;

    // --- phase 1: GEMV over input chunks ---
    while (true) {
        if (tid == 0) s_chunk = atomicAdd(&g_work, 1);
        __syncthreads();
        int c = s_chunk;
        if (c >= N_CHUNK) break;
        int rowBase = c * ROWS_PER_CHUNK;

        for (int bt = 0; bt < 4; bt++) {
            int r0 = rowBase + bt * 8;
            float4 xr[8];
#pragma unroll
            for (int r = 0; r < 8; r++)
                xr[r] = __ldcs(&in4[(size_t)(r0 + r) * 256 + tid]);
#pragma unroll
            for (int r = 0; r < 8; r++) {
                float4 x = xr[r];
                float a0 = fmaf(x.x, w0.x, fmaf(x.y, w0.y, fmaf(x.z, w0.z, x.w * w0.w)));
                float a1 = fmaf(x.x, w1.x, fmaf(x.y, w1.y, fmaf(x.z, w1.z, x.w * w1.w)));
                float a2 = fmaf(x.x, w2.x, fmaf(x.y, w2.y, fmaf(x.z, w2.z, x.w * w2.w)));
                float a3 = fmaf(x.x, w3.x, fmaf(x.y, w3.y, fmaf(x.z, w3.z, x.w * w3.w)));
                // packed tree: demultiplex the 4 k's during the reduction
                float o0 = __shfl_xor_sync(0xffffffffu, a0, 16);
                float o1 = __shfl_xor_sync(0xffffffffu, a1, 16);
                float o2 = __shfl_xor_sync(0xffffffffu, a2, 16);
                float o3 = __shfl_xor_sync(0xffffffffu, a3, 16);
                bool hi = lane >= 16;
                float b0 = hi ? (a2 + o2) : (a0 + o0);
                float b1 = hi ? (a3 + o3) : (a1 + o1);
                float q0 = __shfl_xor_sync(0xffffffffu, b0, 8);
                float q1 = __shfl_xor_sync(0xffffffffu, b1, 8);
                float cc = (lane & 8) ? (b1 + q1) : (b0 + q0);
                cc += __shfl_xor_sync(0xffffffffu, cc, 4);
                cc += __shfl_xor_sync(0xffffffffu, cc, 2);
                cc += __shfl_xor_sync(0xffffffffu, cc, 1);
                if ((lane & 7) == 0) red[r][lane >> 3][wid] = cc;
            }
            __syncthreads();
            if (tid < 32) {
                int r = tid >> 2, k = tid & 3;
                float v = 0.f;
#pragma unroll
                for (int w = 0; w < 8; w++) v += red[r][k][w];
                g_xq[(size_t)(r0 + r) * 4 + k] = v + g_coef[4 + k];
            }
            __syncthreads();
        }
        if (tid == 0) {
            __threadfence();
            atomicAdd(&g_ready[c >> 2], 1);   // t = chunk/4
        }
    }

    // --- phase 2: output broadcast, gated on rec frontier ---
    float4* o4 = (float4*)out;
    while (true) {
        if (tid == 0) s_chunk = atomicAdd(&g_owork, 1);
        __syncthreads();
        int c = s_chunk;
        if (c >= N_OCHUNK) break;
        int row0 = c * 32;
        int lastRow = row0 + 31;
        int need = (lastRow < TB) ? ((lastRow >> 7) + 1) : (T_STEPS + 1);
        if (tid == 0) wait_gfront(&g_outfront, need);
        __syncthreads();
#pragma unroll 4
        for (int r = 0; r < 32; r++) {
            int row = row0 + r;
            float v = (row < TB) ? __ldcg(&g_Hs[row]) : __ldcg(&g_fin[row - TB]);
            float4 vv = make_float4(v, v, v, v);
            __stcs(&o4[(size_t)row * 256 + tid], vv);
        }
    }
}

// ---------------- launch ----------------
extern "C" void kernel_launch(void* const* d_in, const int* in_sizes, int n_in,
                              void* d_out, int out_size) {
    const float* inputs = (const float*)d_in[0];
    const float* Wi     = (const float*)d_in[1];
    const float* bi     = (const float*)d_in[2];
    const float* Wh     = (const float*)d_in[3];
    const float* bh     = (const float*)d_in[4];
    const float* Wq     = (const float*)d_in[5];
    const float* bq     = (const float*)d_in[6];
    const float* theta  = (const float*)d_in[7];
    float* out = (float*)d_out;

    k_pre1<<<H_SZ + 128, 256>>>(Wh, bi, bh, Wi, Wq);
    k_pre2<<<20, 256>>>(Wq, bq, theta);
    k_main<<<N_WORK + 1, 256>>>(inputs, out);
}